// round 3
// baseline (speedup 1.0000x reference)
#include <cuda_runtime.h>
#include <math.h>

#define BB 256
#define FF 256
#define DD 512
#define NJ3v 51
#define INDIM 34
#define G4 2048       // 4*D gate rows
#define KTOT 1024     // packed K (512 + 512)
#define MCW 563       // D + NJ3

// ---------------- static device scratch (no runtime allocation) ----------------
__device__ float g_Xp[(size_t)BB * FF * G4];   // 512 MB: per-(t,b) gate base
__device__ float g_WA[(size_t)G4 * KTOT];      // [Whh0 | Wcomb]
__device__ float g_WB[(size_t)G4 * KTOT];      // [Wih1 | Whh1]
__device__ float g_Wx[INDIM * G4];             // embed_W @ Wih0x^T
__device__ float g_bx[G4];
__device__ float g_cpred[G4];                  // dec_b @ Wih0pred^T
__device__ float g_bias1[G4];
__device__ float g_p0c[BB * G4];               // pred0 @ Wih0pred^T
__device__ float g_h0[2][BB * DD];
__device__ float g_h1[2][BB * DD];
__device__ float g_c0[BB * DD];
__device__ float g_c1[BB * DD];
__device__ float g_z1[BB * DD];
__device__ float g_z2[BB * 1024];

// ---------------- helpers ----------------
__device__ __forceinline__ float sigf(float x) { return 1.0f / (1.0f + expf(-x)); }

__device__ __forceinline__ unsigned long long pack2(float x, float y) {
    unsigned long long r;
    asm("mov.b64 %0, {%1, %2};" : "=l"(r) : "f"(x), "f"(y));
    return r;
}
__device__ __forceinline__ void ffma2(unsigned long long& a, unsigned long long b, unsigned long long c) {
    asm("fma.rn.f32x2 %0, %1, %2, %0;" : "+l"(a) : "l"(b), "l"(c));
}
__device__ __forceinline__ float lo2(unsigned long long v) { return __uint_as_float((unsigned)v); }
__device__ __forceinline__ float hi2(unsigned long long v) { return __uint_as_float((unsigned)(v >> 32)); }

// ---------------- one-time precompute kernels ----------------

// Wx[i][j] = sum_k embed_W[i,k] * Wih0[j,k]   (k < 512)
__global__ void wx_kernel(const float* __restrict__ embed_W, const float* __restrict__ Wih0) {
    int idx = blockIdx.x * 256 + threadIdx.x;
    if (idx >= INDIM * G4) return;
    int i = idx / G4, j = idx % G4;
    float s = 0.f;
    const float* wr = Wih0 + (size_t)j * MCW;
    const float* er = embed_W + (size_t)i * DD;
    for (int k = 0; k < DD; k++) s += er[k] * wr[k];
    g_Wx[idx] = s;
}

// bx[j] = embed_b @ Wih0x^T + bih0 + bhh0 ; cpred[j] = dec_b @ Wih0pred^T ; bias1
__global__ void bias_kernel(const float* __restrict__ embed_b, const float* __restrict__ Wih0,
                            const float* __restrict__ bih0, const float* __restrict__ bhh0,
                            const float* __restrict__ bih1, const float* __restrict__ bhh1,
                            const float* __restrict__ dec_b) {
    int j = blockIdx.x * 256 + threadIdx.x;
    if (j >= G4) return;
    const float* wr = Wih0 + (size_t)j * MCW;
    float s = bih0[j] + bhh0[j];
    for (int k = 0; k < DD; k++) s += embed_b[k] * wr[k];
    g_bx[j] = s;
    float cp = 0.f;
    for (int m = 0; m < NJ3v; m++) cp += dec_b[m] * wr[DD + m];
    g_cpred[j] = cp;
    g_bias1[j] = bih1[j] + bhh1[j];
}

// p0c[b][j] = pred0[b] @ Wih0pred^T   (pred0 = init[b,0,:51])
__global__ void p0c_kernel(const float* __restrict__ initp, const float* __restrict__ Wih0) {
    int idx = blockIdx.x * 256 + threadIdx.x;  // BB*G4
    int b = idx >> 11, j = idx & (G4 - 1);
    const float* wr = Wih0 + (size_t)j * MCW + DD;
    const float* p0 = initp + (size_t)b * 85;
    float s = 0.f;
    for (int m = 0; m < NJ3v; m++) s += p0[m] * wr[m];
    g_p0c[idx] = s;
}

// WA = [Whh0 | Wcomb],  Wcomb[j][k] = sum_m Wih0[j,512+m] * dec_W[k,m]
__global__ void packA_kernel(const float* __restrict__ Whh0, const float* __restrict__ Wih0,
                             const float* __restrict__ dec_W) {
    int idx = blockIdx.x * 256 + threadIdx.x;  // G4*KTOT
    int j = idx >> 10, k = idx & (KTOT - 1);
    float v;
    if (k < DD) {
        v = Whh0[(size_t)j * DD + k];
    } else {
        int kk = k - DD;
        const float* wr = Wih0 + (size_t)j * MCW + DD;
        const float* dr = dec_W + (size_t)kk * NJ3v;
        float s = 0.f;
        for (int m = 0; m < NJ3v; m++) s += wr[m] * dr[m];
        v = s;
    }
    g_WA[idx] = v;
}

__global__ void packB_kernel(const float* __restrict__ Wih1, const float* __restrict__ Whh1) {
    int idx = blockIdx.x * 256 + threadIdx.x;
    int j = idx >> 10, k = idx & (KTOT - 1);
    g_WB[idx] = (k < DD) ? Wih1[(size_t)j * DD + k] : Whh1[(size_t)j * DD + (k - DD)];
}

// init-net MLP
__global__ void init1_kernel(const float* __restrict__ initp, const float* __restrict__ W,
                             const float* __restrict__ b) {
    int idx = blockIdx.x * 256 + threadIdx.x;  // BB*DD
    int bb = idx >> 9, j = idx & (DD - 1);
    float s = b[j];
    const float* ir = initp + (size_t)bb * 85;
    for (int i = 0; i < 85; i++) s += ir[i] * W[(size_t)i * DD + j];
    g_z1[idx] = fmaxf(s, 0.f);
}
__global__ void init2_kernel(const float* __restrict__ W, const float* __restrict__ b) {
    int idx = blockIdx.x * 256 + threadIdx.x;  // BB*1024
    int bb = idx >> 10, j = idx & 1023;
    float s = b[j];
    const float* zr = g_z1 + (size_t)bb * DD;
    for (int k = 0; k < DD; k++) s += zr[k] * W[(size_t)k * 1024 + j];
    g_z2[idx] = fmaxf(s, 0.f);
}
__global__ void init3_kernel(const float* __restrict__ W, const float* __restrict__ b) {
    int idx = blockIdx.x * 256 + threadIdx.x;  // BB*G4
    int bb = idx >> 11, j = idx & (G4 - 1);
    float s = b[j];
    const float* zr = g_z2 + (size_t)bb * 1024;
    for (int k = 0; k < 1024; k++) s += zr[k] * W[(size_t)k * G4 + j];
    // z.reshape(b,2,L,D): [b][0][l][d] -> h layer l ; [b][1][l][d] -> c layer l
    if (j < DD)            g_h0[0][(size_t)bb * DD + j] = s;
    else if (j < 2 * DD)   g_h1[0][(size_t)bb * DD + (j - DD)] = s;
    else if (j < 3 * DD)   g_c0[(size_t)bb * DD + (j - 2 * DD)] = s;
    else                   g_c1[(size_t)bb * DD + (j - 3 * DD)] = s;
}

// Xp[row=t*B+b][j] = x[b,t,:] @ Wx[:,j] + bx[j] + (t==0 ? p0c[b][j] : cpred[j])
__global__ void xp_kernel(const float* __restrict__ x) {
    __shared__ float sX[32][INDIM];
    int j = blockIdx.x * 256 + threadIdx.x;  // grid.x = 8
    int r0 = blockIdx.y * 32;
    for (int idx = threadIdx.x; idx < 32 * INDIM; idx += 256) {
        int r = idx / INDIM, i = idx % INDIM;
        int row = r0 + r;
        int tt = row >> 8, b = row & 255;
        sX[r][i] = x[((size_t)b * FF + tt) * INDIM + i];
    }
    __syncthreads();
    float wcol[INDIM];
#pragma unroll
    for (int i = 0; i < INDIM; i++) wcol[i] = g_Wx[i * G4 + j];
    float bxj = g_bx[j], cpj = g_cpred[j];
    for (int r = 0; r < 32; r++) {
        int row = r0 + r;
        int tt = row >> 8, b = row & 255;
        float acc = bxj + ((tt == 0) ? g_p0c[(size_t)b * G4 + j] : cpj);
#pragma unroll
        for (int i = 0; i < INDIM; i++) acc += sX[r][i] * wcol[i];
        g_Xp[(size_t)row * G4 + j] = acc;
    }
}

// ---------------- the recurrent step kernel (GEMM + fused LSTM cell) ----------------
// gates[b][g*512+d] = base + sum_{k<1024} in[b][k] * W[g*512+d][k],   in = concat(in0,in1)
// then cell update: c' = sig(f)*c + sig(i)*tanh(g); h = sig(o)*tanh(c')
__global__ __launch_bounds__(256) void lstm_step(
    const float* __restrict__ W, const float* __restrict__ in0, const float* __restrict__ in1,
    const float* __restrict__ base, int bstride,
    float* __restrict__ cst, float* __restrict__ hout, float* __restrict__ mc, int t) {
    __shared__ float sIn[32][34];    // [k][b], padded to 34 (8B-aligned float2 reads)
    __shared__ float sW[128][33];    // [4g*32d][k], padded -> conflict-free

    const int tid = threadIdx.x;
    const int tx = tid & 31;   // d_local
    const int bg = tid >> 5;   // batch group 0..7 (4 rows each)
    const int d0 = blockIdx.x * 32;
    const int b0 = blockIdx.y * 32;

    unsigned long long acc[4][2];
#pragma unroll
    for (int g = 0; g < 4; g++) {
        acc[g][0] = 0ull; acc[g][1] = 0ull;
    }

    for (int kt = 0; kt < KTOT; kt += 32) {
        // stage input tile (transposed): sIn[k][b]
#pragma unroll
        for (int l = 0; l < 4; l++) {
            int idx = tid + l * 256;           // 0..1023
            int bl = idx >> 5, kl = idx & 31;
            int k = kt + kl;
            float v = (k < DD) ? in0[(size_t)(b0 + bl) * DD + k]
                               : in1[(size_t)(b0 + bl) * DD + (k - DD)];
            sIn[kl][bl] = v;
        }
        // stage weight tile: 128 gate-rows x 32 k
#pragma unroll
        for (int l = 0; l < 16; l++) {
            int idx = tid + l * 256;           // 0..4095
            int row = idx >> 5, col = idx & 31;
            int g = row >> 5, r = row & 31;
            sW[row][col] = W[(size_t)(g * DD + d0 + r) * KTOT + kt + col];
        }
        __syncthreads();
#pragma unroll
        for (int k = 0; k < 32; k++) {
            unsigned long long i0 = *(const unsigned long long*)&sIn[k][bg * 4];
            unsigned long long i1 = *(const unsigned long long*)&sIn[k][bg * 4 + 2];
#pragma unroll
            for (int g = 0; g < 4; g++) {
                float w = sW[g * 32 + tx][k];
                unsigned long long w2 = pack2(w, w);
                ffma2(acc[g][0], i0, w2);
                ffma2(acc[g][1], i1, w2);
            }
        }
        __syncthreads();
    }

    // epilogue: LSTM cell for 4 batch rows
    const int d = d0 + tx;
#pragma unroll
    for (int p = 0; p < 4; p++) {
        int b = b0 + bg * 4 + p;
        int pair = p >> 1, lane = p & 1;
        float gi = lane ? hi2(acc[0][pair]) : lo2(acc[0][pair]);
        float gf = lane ? hi2(acc[1][pair]) : lo2(acc[1][pair]);
        float gg = lane ? hi2(acc[2][pair]) : lo2(acc[2][pair]);
        float go = lane ? hi2(acc[3][pair]) : lo2(acc[3][pair]);
        const float* brow = base + (size_t)b * bstride;
        gi += brow[0 * DD + d];
        gf += brow[1 * DD + d];
        gg += brow[2 * DD + d];
        go += brow[3 * DD + d];
        size_t idx = (size_t)b * DD + d;
        float cn = sigf(gf) * cst[idx] + sigf(gi) * tanhf(gg);
        cst[idx] = cn;
        float h = sigf(go) * tanhf(cn);
        hout[idx] = h;
        if (mc) mc[((size_t)b * FF + t) * MCW + d] = h;
    }
}

// ---------------- final decode: preds from stored h1 context ----------------
__global__ __launch_bounds__(256) void dec_kernel(const float* __restrict__ dec_W,
                                                  const float* __restrict__ dec_b,
                                                  float* __restrict__ out_kp, float* __restrict__ mc) {
    __shared__ float sh[4][DD];
    size_t row0 = (size_t)blockIdx.x * 4;
    for (int idx = threadIdx.x; idx < 4 * DD; idx += 256)
        sh[idx >> 9][idx & (DD - 1)] = mc[(row0 + (idx >> 9)) * MCW + (idx & (DD - 1))];
    __syncthreads();
    int r = threadIdx.x >> 6, c = threadIdx.x & 63;
    if (c < NJ3v) {
        float s = dec_b[c];
        for (int k = 0; k < DD; k++) s += sh[r][k] * dec_W[(size_t)k * NJ3v + c];
        size_t row = row0 + r;
        out_kp[row * NJ3v + c] = s;
        mc[row * MCW + DD + c] = s;
    }
}

// ---------------- launch ----------------
extern "C" void kernel_launch(void* const* d_in, const int* in_sizes, int n_in,
                              void* d_out, int out_size) {
    const float* x       = (const float*)d_in[0];
    const float* initp   = (const float*)d_in[1];
    const float* embed_W = (const float*)d_in[2];
    const float* embed_b = (const float*)d_in[3];
    const float* ni_W1   = (const float*)d_in[4];
    const float* ni_b1   = (const float*)d_in[5];
    const float* ni_W2   = (const float*)d_in[6];
    const float* ni_b2   = (const float*)d_in[7];
    const float* ni_W3   = (const float*)d_in[8];
    const float* ni_b3   = (const float*)d_in[9];
    const float* Wih0    = (const float*)d_in[10];
    const float* Whh0    = (const float*)d_in[11];
    const float* bih0    = (const float*)d_in[12];
    const float* bhh0    = (const float*)d_in[13];
    const float* Wih1    = (const float*)d_in[14];
    const float* Whh1    = (const float*)d_in[15];
    const float* bih1    = (const float*)d_in[16];
    const float* bhh1    = (const float*)d_in[17];
    const float* dec_W   = (const float*)d_in[18];
    const float* dec_b   = (const float*)d_in[19];

    float* out = (float*)d_out;
    float* kp = out;                                  // (B,F,17,3)
    float* mc = out + (size_t)BB * FF * NJ3v;         // (B,F,563)

    float *Xp, *WA, *WB, *h0, *h1, *c0, *c1, *bias1v;
    cudaGetSymbolAddress((void**)&Xp, g_Xp);
    cudaGetSymbolAddress((void**)&WA, g_WA);
    cudaGetSymbolAddress((void**)&WB, g_WB);
    cudaGetSymbolAddress((void**)&h0, g_h0);
    cudaGetSymbolAddress((void**)&h1, g_h1);
    cudaGetSymbolAddress((void**)&c0, g_c0);
    cudaGetSymbolAddress((void**)&c1, g_c1);
    cudaGetSymbolAddress((void**)&bias1v, g_bias1);

    // one-time precompute (parallel)
    wx_kernel<<<272, 256>>>(embed_W, Wih0);
    bias_kernel<<<8, 256>>>(embed_b, Wih0, bih0, bhh0, bih1, bhh1, dec_b);
    p0c_kernel<<<2048, 256>>>(initp, Wih0);
    packA_kernel<<<8192, 256>>>(Whh0, Wih0, dec_W);
    packB_kernel<<<8192, 256>>>(Wih1, Whh1);
    init1_kernel<<<512, 256>>>(initp, ni_W1, ni_b1);
    init2_kernel<<<1024, 256>>>(ni_W2, ni_b2);
    init3_kernel<<<2048, 256>>>(ni_W3, ni_b3);
    xp_kernel<<<dim3(8, 2048), 256>>>(x);

    // sequential recurrence: 2 fused GEMM+cell kernels per step
    dim3 gridS(16, 8);  // 16 d-tiles x 8 b-tiles = 128 blocks
    const size_t HSZ = (size_t)BB * DD;
    for (int t = 0; t < FF; t++) {
        int p = t & 1;
        lstm_step<<<gridS, 256>>>(WA, h0 + (size_t)p * HSZ, h1 + (size_t)p * HSZ,
                                  Xp + (size_t)t * BB * G4, G4,
                                  c0, h0 + (size_t)(1 - p) * HSZ, nullptr, t);
        lstm_step<<<gridS, 256>>>(WB, h0 + (size_t)(1 - p) * HSZ, h1 + (size_t)p * HSZ,
                                  bias1v, 0,
                                  c1, h1 + (size_t)(1 - p) * HSZ, mc, t);
    }

    // final decode of preds for all (b,t)
    dec_kernel<<<16384, 256>>>(dec_W, dec_b, kp, mc);
}

// round 4
// speedup vs baseline: 1.0000x; 1.0000x over previous
#include <cuda_runtime.h>
#include <math.h>

#define BB 256
#define FF 256
#define DD 512
#define NJ3v 51
#define INDIM 34
#define G4 2048       // 4*D gate rows
#define KTOT 1024     // packed K (512 + 512)
#define MCW 563       // D + NJ3

// ---------------- static device scratch (no runtime allocation) ----------------
__device__ float g_Xp[(size_t)BB * FF * G4];   // 512 MB: per-(t,b) gate base
__device__ float g_WA[(size_t)G4 * KTOT];      // [Whh0 | Wcomb]
__device__ float g_WB[(size_t)G4 * KTOT];      // [Wih1 | Whh1]
__device__ float g_Wx[INDIM * G4];             // embed_W @ Wih0x^T
__device__ float g_bx[G4];
__device__ float g_cpred[G4];                  // dec_b @ Wih0pred^T
__device__ float g_bias1[G4];
__device__ float g_p0c[BB * G4];               // pred0 @ Wih0pred^T
__device__ float g_h0[2][BB * DD];
__device__ float g_h1[2][BB * DD];
__device__ float g_c0[BB * DD];
__device__ float g_c1[BB * DD];
__device__ float g_z1[BB * DD];
__device__ float g_z2[BB * 1024];

// ---------------- helpers ----------------
__device__ __forceinline__ float sigf(float x) { return 1.0f / (1.0f + expf(-x)); }

__device__ __forceinline__ unsigned long long pack2(float x, float y) {
    unsigned long long r;
    asm("mov.b64 %0, {%1, %2};" : "=l"(r) : "f"(x), "f"(y));
    return r;
}
__device__ __forceinline__ void ffma2(unsigned long long& a, unsigned long long b, unsigned long long c) {
    asm("fma.rn.f32x2 %0, %1, %2, %0;" : "+l"(a) : "l"(b), "l"(c));
}
__device__ __forceinline__ float lo2(unsigned long long v) { return __uint_as_float((unsigned)v); }
__device__ __forceinline__ float hi2(unsigned long long v) { return __uint_as_float((unsigned)(v >> 32)); }

// ---------------- one-time precompute kernels ----------------

// Wx[i][j] = sum_k embed_W[i,k] * Wih0[j,k]   (k < 512)
__global__ void wx_kernel(const float* __restrict__ embed_W, const float* __restrict__ Wih0) {
    int idx = blockIdx.x * 256 + threadIdx.x;
    if (idx >= INDIM * G4) return;
    int i = idx / G4, j = idx % G4;
    float s = 0.f;
    const float* wr = Wih0 + (size_t)j * MCW;
    const float* er = embed_W + (size_t)i * DD;
    for (int k = 0; k < DD; k++) s += er[k] * wr[k];
    g_Wx[idx] = s;
}

// bx[j] = embed_b @ Wih0x^T + bih0 + bhh0 ; cpred[j] = dec_b @ Wih0pred^T ; bias1
__global__ void bias_kernel(const float* __restrict__ embed_b, const float* __restrict__ Wih0,
                            const float* __restrict__ bih0, const float* __restrict__ bhh0,
                            const float* __restrict__ bih1, const float* __restrict__ bhh1,
                            const float* __restrict__ dec_b) {
    int j = blockIdx.x * 256 + threadIdx.x;
    if (j >= G4) return;
    const float* wr = Wih0 + (size_t)j * MCW;
    float s = bih0[j] + bhh0[j];
    for (int k = 0; k < DD; k++) s += embed_b[k] * wr[k];
    g_bx[j] = s;
    float cp = 0.f;
    for (int m = 0; m < NJ3v; m++) cp += dec_b[m] * wr[DD + m];
    g_cpred[j] = cp;
    g_bias1[j] = bih1[j] + bhh1[j];
}

// p0c[b][j] = pred0[b] @ Wih0pred^T   (pred0 = init[b,0,:51])
__global__ void p0c_kernel(const float* __restrict__ initp, const float* __restrict__ Wih0) {
    int idx = blockIdx.x * 256 + threadIdx.x;  // BB*G4
    int b = idx >> 11, j = idx & (G4 - 1);
    const float* wr = Wih0 + (size_t)j * MCW + DD;
    const float* p0 = initp + (size_t)b * 85;
    float s = 0.f;
    for (int m = 0; m < NJ3v; m++) s += p0[m] * wr[m];
    g_p0c[idx] = s;
}

// WA = [Whh0 | Wcomb],  Wcomb[j][k] = sum_m Wih0[j,512+m] * dec_W[k,m]
__global__ void packA_kernel(const float* __restrict__ Whh0, const float* __restrict__ Wih0,
                             const float* __restrict__ dec_W) {
    int idx = blockIdx.x * 256 + threadIdx.x;  // G4*KTOT
    int j = idx >> 10, k = idx & (KTOT - 1);
    float v;
    if (k < DD) {
        v = Whh0[(size_t)j * DD + k];
    } else {
        int kk = k - DD;
        const float* wr = Wih0 + (size_t)j * MCW + DD;
        const float* dr = dec_W + (size_t)kk * NJ3v;
        float s = 0.f;
        for (int m = 0; m < NJ3v; m++) s += wr[m] * dr[m];
        v = s;
    }
    g_WA[idx] = v;
}

__global__ void packB_kernel(const float* __restrict__ Wih1, const float* __restrict__ Whh1) {
    int idx = blockIdx.x * 256 + threadIdx.x;
    int j = idx >> 10, k = idx & (KTOT - 1);
    g_WB[idx] = (k < DD) ? Wih1[(size_t)j * DD + k] : Whh1[(size_t)j * DD + (k - DD)];
}

// init-net MLP
__global__ void init1_kernel(const float* __restrict__ initp, const float* __restrict__ W,
                             const float* __restrict__ b) {
    int idx = blockIdx.x * 256 + threadIdx.x;  // BB*DD
    int bb = idx >> 9, j = idx & (DD - 1);
    float s = b[j];
    const float* ir = initp + (size_t)bb * 85;
    for (int i = 0; i < 85; i++) s += ir[i] * W[(size_t)i * DD + j];
    g_z1[idx] = fmaxf(s, 0.f);
}
__global__ void init2_kernel(const float* __restrict__ W, const float* __restrict__ b) {
    int idx = blockIdx.x * 256 + threadIdx.x;  // BB*1024
    int bb = idx >> 10, j = idx & 1023;
    float s = b[j];
    const float* zr = g_z1 + (size_t)bb * DD;
    for (int k = 0; k < DD; k++) s += zr[k] * W[(size_t)k * 1024 + j];
    g_z2[idx] = fmaxf(s, 0.f);
}
__global__ void init3_kernel(const float* __restrict__ W, const float* __restrict__ b) {
    int idx = blockIdx.x * 256 + threadIdx.x;  // BB*G4
    int bb = idx >> 11, j = idx & (G4 - 1);
    float s = b[j];
    const float* zr = g_z2 + (size_t)bb * 1024;
    for (int k = 0; k < 1024; k++) s += zr[k] * W[(size_t)k * G4 + j];
    // z.reshape(b,2,L,D): [b][0][l][d] -> h layer l ; [b][1][l][d] -> c layer l
    if (j < DD)            g_h0[0][(size_t)bb * DD + j] = s;
    else if (j < 2 * DD)   g_h1[0][(size_t)bb * DD + (j - DD)] = s;
    else if (j < 3 * DD)   g_c0[(size_t)bb * DD + (j - 2 * DD)] = s;
    else                   g_c1[(size_t)bb * DD + (j - 3 * DD)] = s;
}

// Xp[row=t*B+b][j] = x[b,t,:] @ Wx[:,j] + bx[j] + (t==0 ? p0c[b][j] : cpred[j])
__global__ void xp_kernel(const float* __restrict__ x) {
    __shared__ float sX[32][INDIM];
    int j = blockIdx.x * 256 + threadIdx.x;  // grid.x = 8
    int r0 = blockIdx.y * 32;
    for (int idx = threadIdx.x; idx < 32 * INDIM; idx += 256) {
        int r = idx / INDIM, i = idx % INDIM;
        int row = r0 + r;
        int tt = row >> 8, b = row & 255;
        sX[r][i] = x[((size_t)b * FF + tt) * INDIM + i];
    }
    __syncthreads();
    float wcol[INDIM];
#pragma unroll
    for (int i = 0; i < INDIM; i++) wcol[i] = g_Wx[i * G4 + j];
    float bxj = g_bx[j], cpj = g_cpred[j];
    for (int r = 0; r < 32; r++) {
        int row = r0 + r;
        int tt = row >> 8, b = row & 255;
        float acc = bxj + ((tt == 0) ? g_p0c[(size_t)b * G4 + j] : cpj);
#pragma unroll
        for (int i = 0; i < INDIM; i++) acc += sX[r][i] * wcol[i];
        g_Xp[(size_t)row * G4 + j] = acc;
    }
}

// ---------------- the recurrent step kernel (GEMM + fused LSTM cell) ----------------
// gates[b][g*512+d] = base + sum_{k<1024} in[b][k] * W[g*512+d][k],   in = concat(in0,in1)
// then cell update: c' = sig(f)*c + sig(i)*tanh(g); h = sig(o)*tanh(c')
__global__ __launch_bounds__(256) void lstm_step(
    const float* __restrict__ W, const float* __restrict__ in0, const float* __restrict__ in1,
    const float* __restrict__ base, int bstride,
    float* __restrict__ cst, float* __restrict__ hout, float* __restrict__ mc, int t) {
    __shared__ float sIn[32][34];    // [k][b], padded to 34 (8B-aligned float2 reads)
    __shared__ float sW[128][33];    // [4g*32d][k], padded -> conflict-free

    const int tid = threadIdx.x;
    const int tx = tid & 31;   // d_local
    const int bg = tid >> 5;   // batch group 0..7 (4 rows each)
    const int d0 = blockIdx.x * 32;
    const int b0 = blockIdx.y * 32;

    unsigned long long acc[4][2];
#pragma unroll
    for (int g = 0; g < 4; g++) {
        acc[g][0] = 0ull; acc[g][1] = 0ull;
    }

    for (int kt = 0; kt < KTOT; kt += 32) {
        // stage input tile (transposed): sIn[k][b]
#pragma unroll
        for (int l = 0; l < 4; l++) {
            int idx = tid + l * 256;           // 0..1023
            int bl = idx >> 5, kl = idx & 31;
            int k = kt + kl;
            float v = (k < DD) ? in0[(size_t)(b0 + bl) * DD + k]
                               : in1[(size_t)(b0 + bl) * DD + (k - DD)];
            sIn[kl][bl] = v;
        }
        // stage weight tile: 128 gate-rows x 32 k
#pragma unroll
        for (int l = 0; l < 16; l++) {
            int idx = tid + l * 256;           // 0..4095
            int row = idx >> 5, col = idx & 31;
            int g = row >> 5, r = row & 31;
            sW[row][col] = W[(size_t)(g * DD + d0 + r) * KTOT + kt + col];
        }
        __syncthreads();
#pragma unroll
        for (int k = 0; k < 32; k++) {
            unsigned long long i0 = *(const unsigned long long*)&sIn[k][bg * 4];
            unsigned long long i1 = *(const unsigned long long*)&sIn[k][bg * 4 + 2];
#pragma unroll
            for (int g = 0; g < 4; g++) {
                float w = sW[g * 32 + tx][k];
                unsigned long long w2 = pack2(w, w);
                ffma2(acc[g][0], i0, w2);
                ffma2(acc[g][1], i1, w2);
            }
        }
        __syncthreads();
    }

    // epilogue: LSTM cell for 4 batch rows
    const int d = d0 + tx;
#pragma unroll
    for (int p = 0; p < 4; p++) {
        int b = b0 + bg * 4 + p;
        int pair = p >> 1, lane = p & 1;
        float gi = lane ? hi2(acc[0][pair]) : lo2(acc[0][pair]);
        float gf = lane ? hi2(acc[1][pair]) : lo2(acc[1][pair]);
        float gg = lane ? hi2(acc[2][pair]) : lo2(acc[2][pair]);
        float go = lane ? hi2(acc[3][pair]) : lo2(acc[3][pair]);
        const float* brow = base + (size_t)b * bstride;
        gi += brow[0 * DD + d];
        gf += brow[1 * DD + d];
        gg += brow[2 * DD + d];
        go += brow[3 * DD + d];
        size_t idx = (size_t)b * DD + d;
        float cn = sigf(gf) * cst[idx] + sigf(gi) * tanhf(gg);
        cst[idx] = cn;
        float h = sigf(go) * tanhf(cn);
        hout[idx] = h;
        if (mc) mc[((size_t)b * FF + t) * MCW + d] = h;
    }
}

// ---------------- final decode: preds from stored h1 context ----------------
__global__ __launch_bounds__(256) void dec_kernel(const float* __restrict__ dec_W,
                                                  const float* __restrict__ dec_b,
                                                  float* __restrict__ out_kp, float* __restrict__ mc) {
    __shared__ float sh[4][DD];
    size_t row0 = (size_t)blockIdx.x * 4;
    for (int idx = threadIdx.x; idx < 4 * DD; idx += 256)
        sh[idx >> 9][idx & (DD - 1)] = mc[(row0 + (idx >> 9)) * MCW + (idx & (DD - 1))];
    __syncthreads();
    int r = threadIdx.x >> 6, c = threadIdx.x & 63;
    if (c < NJ3v) {
        float s = dec_b[c];
        for (int k = 0; k < DD; k++) s += sh[r][k] * dec_W[(size_t)k * NJ3v + c];
        size_t row = row0 + r;
        out_kp[row * NJ3v + c] = s;
        mc[row * MCW + DD + c] = s;
    }
}

// ---------------- launch ----------------
extern "C" void kernel_launch(void* const* d_in, const int* in_sizes, int n_in,
                              void* d_out, int out_size) {
    const float* x       = (const float*)d_in[0];
    const float* initp   = (const float*)d_in[1];
    const float* embed_W = (const float*)d_in[2];
    const float* embed_b = (const float*)d_in[3];
    const float* ni_W1   = (const float*)d_in[4];
    const float* ni_b1   = (const float*)d_in[5];
    const float* ni_W2   = (const float*)d_in[6];
    const float* ni_b2   = (const float*)d_in[7];
    const float* ni_W3   = (const float*)d_in[8];
    const float* ni_b3   = (const float*)d_in[9];
    const float* Wih0    = (const float*)d_in[10];
    const float* Whh0    = (const float*)d_in[11];
    const float* bih0    = (const float*)d_in[12];
    const float* bhh0    = (const float*)d_in[13];
    const float* Wih1    = (const float*)d_in[14];
    const float* Whh1    = (const float*)d_in[15];
    const float* bih1    = (const float*)d_in[16];
    const float* bhh1    = (const float*)d_in[17];
    const float* dec_W   = (const float*)d_in[18];
    const float* dec_b   = (const float*)d_in[19];

    float* out = (float*)d_out;
    float* kp = out;                                  // (B,F,17,3)
    float* mc = out + (size_t)BB * FF * NJ3v;         // (B,F,563)

    float *Xp, *WA, *WB, *h0, *h1, *c0, *c1, *bias1v;
    cudaGetSymbolAddress((void**)&Xp, g_Xp);
    cudaGetSymbolAddress((void**)&WA, g_WA);
    cudaGetSymbolAddress((void**)&WB, g_WB);
    cudaGetSymbolAddress((void**)&h0, g_h0);
    cudaGetSymbolAddress((void**)&h1, g_h1);
    cudaGetSymbolAddress((void**)&c0, g_c0);
    cudaGetSymbolAddress((void**)&c1, g_c1);
    cudaGetSymbolAddress((void**)&bias1v, g_bias1);

    // one-time precompute (parallel)
    wx_kernel<<<272, 256>>>(embed_W, Wih0);
    bias_kernel<<<8, 256>>>(embed_b, Wih0, bih0, bhh0, bih1, bhh1, dec_b);
    p0c_kernel<<<2048, 256>>>(initp, Wih0);
    packA_kernel<<<8192, 256>>>(Whh0, Wih0, dec_W);
    packB_kernel<<<8192, 256>>>(Wih1, Whh1);
    init1_kernel<<<512, 256>>>(initp, ni_W1, ni_b1);
    init2_kernel<<<1024, 256>>>(ni_W2, ni_b2);
    init3_kernel<<<2048, 256>>>(ni_W3, ni_b3);
    xp_kernel<<<dim3(8, 2048), 256>>>(x);

    // sequential recurrence: 2 fused GEMM+cell kernels per step
    dim3 gridS(16, 8);  // 16 d-tiles x 8 b-tiles = 128 blocks
    const size_t HSZ = (size_t)BB * DD;
    for (int t = 0; t < FF; t++) {
        int p = t & 1;
        lstm_step<<<gridS, 256>>>(WA, h0 + (size_t)p * HSZ, h1 + (size_t)p * HSZ,
                                  Xp + (size_t)t * BB * G4, G4,
                                  c0, h0 + (size_t)(1 - p) * HSZ, nullptr, t);
        lstm_step<<<gridS, 256>>>(WB, h0 + (size_t)(1 - p) * HSZ, h1 + (size_t)p * HSZ,
                                  bias1v, 0,
                                  c1, h1 + (size_t)(1 - p) * HSZ, mc, t);
    }

    // final decode of preds for all (b,t)
    dec_kernel<<<16384, 256>>>(dec_W, dec_b, kp, mc);
}

// round 5
// speedup vs baseline: 1.1042x; 1.1042x over previous
#include <cuda_runtime.h>
#include <math.h>

#define BB 256
#define FF 256
#define DD 512
#define NJ3v 51
#define INDIM 34
#define G4 2048       // 4*D gate rows
#define KTOT 1024     // packed K (512 + 512)
#define MCW 563       // D + NJ3
#define NBLK 128
#define NTHR 256

// ---------------- static device scratch (no runtime allocation) ----------------
__device__ float g_Xp[(size_t)BB * FF * G4];   // per-(t,b) gate base
__device__ float g_WA[(size_t)G4 * KTOT];      // [Whh0 | Wcomb]
__device__ float g_WB[(size_t)G4 * KTOT];      // [Wih1 | Whh1]
__device__ float g_Wx[INDIM * G4];             // embed_W @ Wih0x^T
__device__ float g_bx[G4];
__device__ float g_cpred[G4];                  // dec_b @ Wih0pred^T
__device__ float g_bias1[G4];
__device__ float g_p0c[BB * G4];               // pred0 @ Wih0pred^T
__device__ float g_h0[2][BB * DD];
__device__ float g_h1[2][BB * DD];
__device__ float g_c0[BB * DD];
__device__ float g_c1[BB * DD];
__device__ float g_z1[BB * DD];
__device__ float g_z2[BB * 1024];
__device__ unsigned g_bar;

// ---------------- helpers ----------------
__device__ __forceinline__ float sigf(float x) { return 1.0f / (1.0f + expf(-x)); }

__device__ __forceinline__ void ffma2(unsigned long long& a, unsigned long long b, unsigned long long c) {
    asm("fma.rn.f32x2 %0, %1, %2, %0;" : "+l"(a) : "l"(b), "l"(c));
}
__device__ __forceinline__ float lo2(unsigned long long v) { return __uint_as_float((unsigned)v); }
__device__ __forceinline__ float hi2(unsigned long long v) { return __uint_as_float((unsigned)(v >> 32)); }

// ---------------- one-time precompute kernels (off critical path) ----------------

__global__ void wx_kernel(const float* __restrict__ embed_W, const float* __restrict__ Wih0) {
    int idx = blockIdx.x * 256 + threadIdx.x;
    if (idx >= INDIM * G4) return;
    int i = idx / G4, j = idx % G4;
    float s = 0.f;
    const float* wr = Wih0 + (size_t)j * MCW;
    const float* er = embed_W + (size_t)i * DD;
    for (int k = 0; k < DD; k++) s += er[k] * wr[k];
    g_Wx[idx] = s;
}

__global__ void bias_kernel(const float* __restrict__ embed_b, const float* __restrict__ Wih0,
                            const float* __restrict__ bih0, const float* __restrict__ bhh0,
                            const float* __restrict__ bih1, const float* __restrict__ bhh1,
                            const float* __restrict__ dec_b) {
    int j = blockIdx.x * 256 + threadIdx.x;
    if (j >= G4) return;
    const float* wr = Wih0 + (size_t)j * MCW;
    float s = bih0[j] + bhh0[j];
    for (int k = 0; k < DD; k++) s += embed_b[k] * wr[k];
    g_bx[j] = s;
    float cp = 0.f;
    for (int m = 0; m < NJ3v; m++) cp += dec_b[m] * wr[DD + m];
    g_cpred[j] = cp;
    g_bias1[j] = bih1[j] + bhh1[j];
}

__global__ void p0c_kernel(const float* __restrict__ initp, const float* __restrict__ Wih0) {
    int idx = blockIdx.x * 256 + threadIdx.x;
    int b = idx >> 11, j = idx & (G4 - 1);
    const float* wr = Wih0 + (size_t)j * MCW + DD;
    const float* p0 = initp + (size_t)b * 85;
    float s = 0.f;
    for (int m = 0; m < NJ3v; m++) s += p0[m] * wr[m];
    g_p0c[idx] = s;
}

__global__ void packA_kernel(const float* __restrict__ Whh0, const float* __restrict__ Wih0,
                             const float* __restrict__ dec_W) {
    int idx = blockIdx.x * 256 + threadIdx.x;
    int j = idx >> 10, k = idx & (KTOT - 1);
    float v;
    if (k < DD) {
        v = Whh0[(size_t)j * DD + k];
    } else {
        int kk = k - DD;
        const float* wr = Wih0 + (size_t)j * MCW + DD;
        const float* dr = dec_W + (size_t)kk * NJ3v;
        float s = 0.f;
        for (int m = 0; m < NJ3v; m++) s += wr[m] * dr[m];
        v = s;
    }
    g_WA[idx] = v;
}

__global__ void packB_kernel(const float* __restrict__ Wih1, const float* __restrict__ Whh1) {
    int idx = blockIdx.x * 256 + threadIdx.x;
    int j = idx >> 10, k = idx & (KTOT - 1);
    g_WB[idx] = (k < DD) ? Wih1[(size_t)j * DD + k] : Whh1[(size_t)j * DD + (k - DD)];
}

__global__ void init1_kernel(const float* __restrict__ initp, const float* __restrict__ W,
                             const float* __restrict__ b) {
    int idx = blockIdx.x * 256 + threadIdx.x;
    int bb = idx >> 9, j = idx & (DD - 1);
    float s = b[j];
    const float* ir = initp + (size_t)bb * 85;
    for (int i = 0; i < 85; i++) s += ir[i] * W[(size_t)i * DD + j];
    g_z1[idx] = fmaxf(s, 0.f);
}
__global__ void init2_kernel(const float* __restrict__ W, const float* __restrict__ b) {
    int idx = blockIdx.x * 256 + threadIdx.x;
    int bb = idx >> 10, j = idx & 1023;
    float s = b[j];
    const float* zr = g_z1 + (size_t)bb * DD;
    for (int k = 0; k < DD; k++) s += zr[k] * W[(size_t)k * 1024 + j];
    g_z2[idx] = fmaxf(s, 0.f);
}
__global__ void init3_kernel(const float* __restrict__ W, const float* __restrict__ b) {
    int idx = blockIdx.x * 256 + threadIdx.x;
    int bb = idx >> 11, j = idx & (G4 - 1);
    float s = b[j];
    const float* zr = g_z2 + (size_t)bb * 1024;
    for (int k = 0; k < 1024; k++) s += zr[k] * W[(size_t)k * G4 + j];
    if (j < DD)            g_h0[0][(size_t)bb * DD + j] = s;
    else if (j < 2 * DD)   g_h1[0][(size_t)bb * DD + (j - DD)] = s;
    else if (j < 3 * DD)   g_c0[(size_t)bb * DD + (j - 2 * DD)] = s;
    else                   g_c1[(size_t)bb * DD + (j - 3 * DD)] = s;
}

__global__ void xp_kernel(const float* __restrict__ x) {
    __shared__ float sX[32][INDIM];
    int j = blockIdx.x * 256 + threadIdx.x;
    int r0 = blockIdx.y * 32;
    for (int idx = threadIdx.x; idx < 32 * INDIM; idx += 256) {
        int r = idx / INDIM, i = idx % INDIM;
        int row = r0 + r;
        int tt = row >> 8, b = row & 255;
        sX[r][i] = x[((size_t)b * FF + tt) * INDIM + i];
    }
    __syncthreads();
    float wcol[INDIM];
#pragma unroll
    for (int i = 0; i < INDIM; i++) wcol[i] = g_Wx[i * G4 + j];
    float bxj = g_bx[j], cpj = g_cpred[j];
    for (int r = 0; r < 32; r++) {
        int row = r0 + r;
        int tt = row >> 8, b = row & 255;
        float acc = bxj + ((tt == 0) ? g_p0c[(size_t)b * G4 + j] : cpj);
#pragma unroll
        for (int i = 0; i < INDIM; i++) acc += sX[r][i] * wcol[i];
        g_Xp[(size_t)row * G4 + j] = acc;
    }
}

// ---------------- persistent recurrent kernel ----------------
// 128 blocks x 256 threads, 1 CTA/SM. Block owns d-slice [4*bid, 4*bid+4):
// 16 gate rows of WA and of WB resident in SMEM for the whole sequence.
// Per phase: stream concat(h,h) inputs L2->SMEM in 64-k tiles, f32x2 GEMM
// (thread = 8 rows x 2 batches), fused LSTM cell; c-state lives in SMEM.

__device__ __forceinline__ void gridbar(unsigned target) {
    __threadfence();
    __syncthreads();
    if (threadIdx.x == 0) {
        unsigned* bp = &g_bar;
        asm volatile("red.release.gpu.add.u32 [%0], 1;" :: "l"(bp) : "memory");
        unsigned v;
        do {
            asm volatile("ld.acquire.gpu.u32 %0, [%1];" : "=r"(v) : "l"(bp) : "memory");
        } while (v < target);
    }
    __syncthreads();
}

__device__ __forceinline__ void do_phase(
    int t, bool isA,
    const float* __restrict__ in0, const float* __restrict__ in1,
    float* __restrict__ hout, float* cell, float* __restrict__ mc,
    const float* sW, float* sIn, float* sG, const float* sBias,
    int tid, int rg, int b0, int d0, int sB)
{
    // gate base init (column = batch = tid)
    if (isA) {
        const float* xr = g_Xp + ((size_t)t * BB + tid) * G4 + d0;
#pragma unroll
        for (int g = 0; g < 4; g++)
#pragma unroll
            for (int dl = 0; dl < 4; dl++)
                sG[(g * 4 + dl) * 256 + tid] = __ldcg(&xr[g * DD + dl]);
    } else {
#pragma unroll
        for (int r = 0; r < 16; r++) sG[r * 256 + tid] = sBias[r];
    }

    unsigned long long acc[8][2];
#pragma unroll
    for (int r = 0; r < 8; r++) { acc[r][0] = 0ull; acc[r][1] = 0ull; }

    for (int kt = 0; kt < KTOT; kt += 64) {
        __syncthreads();   // protect sIn (prev consumers) and order sG init
        // stage input tile [256 b][64 k], XOR-swizzled on k-pairs
        const float* srcb = (kt < DD) ? in0 : (in1 - DD);
#pragma unroll
        for (int it = 0; it < 16; it++) {
            int e = tid + it * 256;
            int b = e >> 4, kc = e & 15;
            float4 v = __ldcg((const float4*)&srcb[(size_t)b * DD + kt + kc * 4]);
            int s = (b >> 1) & 15;
            int base = b * 64;
            *(float2*)&sIn[base + (((kc * 2) ^ s) << 1)]     = make_float2(v.x, v.y);
            *(float2*)&sIn[base + (((kc * 2 + 1) ^ s) << 1)] = make_float2(v.z, v.w);
        }
        __syncthreads();
        const float* wrow = sW + rg * 8 * KTOT + kt;
        const float* ib = sIn + b0 * 64;
#pragma unroll
        for (int q = 0; q < 16; q++) {
            int off0 = ((2 * q) ^ sB) << 1;
            int off1 = ((2 * q + 1) ^ sB) << 1;
            unsigned long long i00 = *(const unsigned long long*)&ib[off0];
            unsigned long long i01 = *(const unsigned long long*)&ib[off1];
            unsigned long long i10 = *(const unsigned long long*)&ib[64 + off0];
            unsigned long long i11 = *(const unsigned long long*)&ib[64 + off1];
#pragma unroll
            for (int r = 0; r < 8; r++) {
                ulonglong2 w = *(const ulonglong2*)&wrow[r * KTOT + q * 4];
                ffma2(acc[r][0], i00, w.x);
                ffma2(acc[r][0], i01, w.y);
                ffma2(acc[r][1], i10, w.x);
                ffma2(acc[r][1], i11, w.y);
            }
        }
    }
    __syncthreads();
    // fold accumulators (owner-exclusive (row,batch) slots)
#pragma unroll
    for (int r = 0; r < 8; r++) {
        int row = rg * 8 + r;
        sG[row * 256 + b0]     += lo2(acc[r][0]) + hi2(acc[r][0]);
        sG[row * 256 + b0 + 1] += lo2(acc[r][1]) + hi2(acc[r][1]);
    }
    __syncthreads();
    // fused LSTM cell: thread = batch tid, 4 d-values
    float hv[4];
#pragma unroll
    for (int dl = 0; dl < 4; dl++) {
        float gi = sG[(0 * 4 + dl) * 256 + tid];
        float gf = sG[(1 * 4 + dl) * 256 + tid];
        float gg = sG[(2 * 4 + dl) * 256 + tid];
        float go = sG[(3 * 4 + dl) * 256 + tid];
        float c  = cell[dl * 256 + tid];
        float cn = sigf(gf) * c + sigf(gi) * tanhf(gg);
        cell[dl * 256 + tid] = cn;
        hv[dl] = sigf(go) * tanhf(cn);
    }
    *(float4*)&hout[(size_t)tid * DD + d0] = make_float4(hv[0], hv[1], hv[2], hv[3]);
    if (mc) {
        float* mr = mc + ((size_t)tid * FF + t) * MCW + d0;
#pragma unroll
        for (int dl = 0; dl < 4; dl++) mr[dl] = hv[dl];
    }
}

__global__ __launch_bounds__(NTHR, 1) void lstm_persist(float* __restrict__ mc) {
    extern __shared__ float sm[];
    float* sWA   = sm;                     // 16*1024
    float* sWB   = sWA + 16 * KTOT;        // 16*1024
    float* sIn   = sWB + 16 * KTOT;        // 256*64
    float* sC    = sIn + 256 * 64;         // 2*4*256
    float* sG    = sC + 2048;              // 16*256
    float* sBias = sG + 16 * 256;          // 16

    const int tid  = threadIdx.x;
    const int lane = tid & 31;
    const int warp = tid >> 5;
    const int rg   = warp & 1;             // row group (8 of 16 rows)
    const int bgrp = warp >> 1;            // batch group (64 batches)
    const int b0   = bgrp * 64 + lane * 2;
    const int d0   = blockIdx.x * 4;
    const int sB   = lane & 15;            // = (b0>>1)&15

    // resident weights: 16 rows each of WA, WB for this d-slice (row = g*4+dl)
#pragma unroll
    for (int it = 0; it < 16; it++) {
        int e = tid + it * 256;            // float4 chunk id, 4096 total
        int r = e >> 8, c = (e & 255) * 4;
        int g = r >> 2, dl = r & 3;
        size_t grow = (size_t)(g * DD + d0 + dl) * KTOT + c;
        *(float4*)&sWA[r * KTOT + c] = __ldcg((const float4*)&g_WA[grow]);
        *(float4*)&sWB[r * KTOT + c] = __ldcg((const float4*)&g_WB[grow]);
    }
    // resident c-state
    {
        float4 c0v = __ldcg((const float4*)&g_c0[(size_t)tid * DD + d0]);
        float4 c1v = __ldcg((const float4*)&g_c1[(size_t)tid * DD + d0]);
        sC[0 * 256 + tid] = c0v.x; sC[1 * 256 + tid] = c0v.y;
        sC[2 * 256 + tid] = c0v.z; sC[3 * 256 + tid] = c0v.w;
        sC[1024 + 0 * 256 + tid] = c1v.x; sC[1024 + 1 * 256 + tid] = c1v.y;
        sC[1024 + 2 * 256 + tid] = c1v.z; sC[1024 + 3 * 256 + tid] = c1v.w;
    }
    if (tid < 16) {
        int g = tid >> 2, dl = tid & 3;
        sBias[tid] = __ldcg(&g_bias1[g * DD + d0 + dl]);
    }
    __syncthreads();

    unsigned ep = 0;
    for (int t = 0; t < FF; t++) {
        int p = t & 1;
        // phase A: layer-0 cell; in = [h0_prev | h1_prev] (Wcomb absorbs pred path)
        do_phase(t, true, g_h0[p], g_h1[p], g_h0[1 - p], sC, nullptr,
                 sWA, sIn, sG, sBias, tid, rg, b0, d0, sB);
        ep++; gridbar(ep * NBLK);
        // phase B: layer-1 cell; in = [h0_new | h1_prev]; h1 -> motion_context
        do_phase(t, false, g_h0[1 - p], g_h1[p], g_h1[1 - p], sC + 1024, mc,
                 sWB, sIn, sG, sBias, tid, rg, b0, d0, sB);
        if (t != FF - 1) { ep++; gridbar(ep * NBLK); }
    }
}

// ---------------- final decode: preds from stored h1 context ----------------
__global__ __launch_bounds__(256) void dec_kernel(const float* __restrict__ dec_W,
                                                  const float* __restrict__ dec_b,
                                                  float* __restrict__ out_kp, float* __restrict__ mc) {
    __shared__ float sh[4][DD];
    size_t row0 = (size_t)blockIdx.x * 4;
    for (int idx = threadIdx.x; idx < 4 * DD; idx += 256)
        sh[idx >> 9][idx & (DD - 1)] = mc[(row0 + (idx >> 9)) * MCW + (idx & (DD - 1))];
    __syncthreads();
    int r = threadIdx.x >> 6, c = threadIdx.x & 63;
    if (c < NJ3v) {
        float s = dec_b[c];
        for (int k = 0; k < DD; k++) s += sh[r][k] * dec_W[(size_t)k * NJ3v + c];
        size_t row = row0 + r;
        out_kp[row * NJ3v + c] = s;
        mc[row * MCW + DD + c] = s;
    }
}

// ---------------- launch ----------------
extern "C" void kernel_launch(void* const* d_in, const int* in_sizes, int n_in,
                              void* d_out, int out_size) {
    const float* x       = (const float*)d_in[0];
    const float* initp   = (const float*)d_in[1];
    const float* embed_W = (const float*)d_in[2];
    const float* embed_b = (const float*)d_in[3];
    const float* ni_W1   = (const float*)d_in[4];
    const float* ni_b1   = (const float*)d_in[5];
    const float* ni_W2   = (const float*)d_in[6];
    const float* ni_b2   = (const float*)d_in[7];
    const float* ni_W3   = (const float*)d_in[8];
    const float* ni_b3   = (const float*)d_in[9];
    const float* Wih0    = (const float*)d_in[10];
    const float* Whh0    = (const float*)d_in[11];
    const float* bih0    = (const float*)d_in[12];
    const float* bhh0    = (const float*)d_in[13];
    const float* Wih1    = (const float*)d_in[14];
    const float* Whh1    = (const float*)d_in[15];
    const float* bih1    = (const float*)d_in[16];
    const float* bhh1    = (const float*)d_in[17];
    const float* dec_W   = (const float*)d_in[18];
    const float* dec_b   = (const float*)d_in[19];

    float* out = (float*)d_out;
    float* kp = out;                                  // (B,F,17,3)
    float* mc = out + (size_t)BB * FF * NJ3v;         // (B,F,563)

    // one-time precompute (parallel)
    wx_kernel<<<272, 256>>>(embed_W, Wih0);
    bias_kernel<<<8, 256>>>(embed_b, Wih0, bih0, bhh0, bih1, bhh1, dec_b);
    p0c_kernel<<<2048, 256>>>(initp, Wih0);
    packA_kernel<<<8192, 256>>>(Whh0, Wih0, dec_W);
    packB_kernel<<<8192, 256>>>(Wih1, Whh1);
    init1_kernel<<<512, 256>>>(initp, ni_W1, ni_b1);
    init2_kernel<<<1024, 256>>>(ni_W2, ni_b2);
    init3_kernel<<<2048, 256>>>(ni_W3, ni_b3);
    xp_kernel<<<dim3(8, 2048), 256>>>(x);

    // reset grid barrier counter (graph-replay deterministic)
    void* barp = nullptr;
    cudaGetSymbolAddress(&barp, g_bar);
    cudaMemsetAsync(barp, 0, sizeof(unsigned));

    // persistent recurrence
    const int SMEM_TOT = (16 * KTOT * 2 + 256 * 64 + 2048 + 16 * 256 + 16) * 4;
    static int attr_set = 0;
    if (!attr_set) {
        cudaFuncSetAttribute(lstm_persist, cudaFuncAttributeMaxDynamicSharedMemorySize, SMEM_TOT);
        attr_set = 1;
    }
    lstm_persist<<<NBLK, NTHR, SMEM_TOT>>>(mc);

    // final decode of preds for all (b,t)
    dec_kernel<<<16384, 256>>>(dec_W, dec_b, kp, mc);
}

// round 8
// speedup vs baseline: 4.4073x; 3.9913x over previous
#include <cuda_runtime.h>
#include <cuda_fp16.h>
#include <math.h>

#define BB 256
#define FF 256
#define DD 512
#define NJ3v 51
#define INDIM 34
#define G4 2048       // 4*D gate rows
#define KTOT 1024     // packed K (512 + 512)
#define MCW 563       // D + NJ3
#define NBLK 128
#define NTHR 256
#define WPADK 1032    // weight SMEM k-stride (pad for conflict-free B-frag loads)
#define APAD 72       // input SMEM k-stride (64 + 8 pad)

// ---------------- static device scratch (no runtime allocation) ----------------
__device__ float g_Xp[(size_t)BB * FF * G4];   // blocked layout [t][dg64][b256][32]
__device__ float g_WA[(size_t)G4 * KTOT];      // [Whh0 | Wcomb]  fp32
__device__ float g_WB[(size_t)G4 * KTOT];      // [Wih1 | Whh1]   fp32
__device__ float g_Wx[INDIM * G4];             // embed_W @ Wih0x^T
__device__ float g_bx[G4];
__device__ float g_cpred[G4];                  // dec_b @ Wih0pred^T
__device__ float g_bias1[G4];
__device__ float g_p0c[BB * G4];               // pred0 @ Wih0pred^T
__device__ __half g_h0[2][BB * DD];            // h states, fp16
__device__ __half g_h1[2][BB * DD];
__device__ float g_c0[BB * DD];
__device__ float g_c1[BB * DD];
__device__ float g_z1[BB * DD];
__device__ float g_z2[BB * 1024];
__device__ unsigned g_bar;

// ---------------- helpers ----------------
__device__ __forceinline__ float sigf(float x) { return 1.0f / (1.0f + expf(-x)); }

__device__ __forceinline__ void mma16816(float* d,
    unsigned a0, unsigned a1, unsigned a2, unsigned a3,
    unsigned b0, unsigned b1) {
    asm volatile(
        "mma.sync.aligned.m16n8k16.row.col.f32.f16.f16.f32 "
        "{%0,%1,%2,%3}, {%4,%5,%6,%7}, {%8,%9}, {%0,%1,%2,%3};"
        : "+f"(d[0]), "+f"(d[1]), "+f"(d[2]), "+f"(d[3])
        : "r"(a0), "r"(a1), "r"(a2), "r"(a3), "r"(b0), "r"(b1));
}

// ---------------- one-time precompute kernels (off critical path) ----------------

__global__ void wx_kernel(const float* __restrict__ embed_W, const float* __restrict__ Wih0) {
    int idx = blockIdx.x * 256 + threadIdx.x;
    if (idx >= INDIM * G4) return;
    int i = idx / G4, j = idx % G4;
    float s = 0.f;
    const float* wr = Wih0 + (size_t)j * MCW;
    const float* er = embed_W + (size_t)i * DD;
    for (int k = 0; k < DD; k++) s += er[k] * wr[k];
    g_Wx[idx] = s;
}

__global__ void bias_kernel(const float* __restrict__ embed_b, const float* __restrict__ Wih0,
                            const float* __restrict__ bih0, const float* __restrict__ bhh0,
                            const float* __restrict__ bih1, const float* __restrict__ bhh1,
                            const float* __restrict__ dec_b) {
    int j = blockIdx.x * 256 + threadIdx.x;
    if (j >= G4) return;
    const float* wr = Wih0 + (size_t)j * MCW;
    float s = bih0[j] + bhh0[j];
    for (int k = 0; k < DD; k++) s += embed_b[k] * wr[k];
    g_bx[j] = s;
    float cp = 0.f;
    for (int m = 0; m < NJ3v; m++) cp += dec_b[m] * wr[DD + m];
    g_cpred[j] = cp;
    g_bias1[j] = bih1[j] + bhh1[j];
}

__global__ void p0c_kernel(const float* __restrict__ initp, const float* __restrict__ Wih0) {
    int idx = blockIdx.x * 256 + threadIdx.x;
    int b = idx >> 11, j = idx & (G4 - 1);
    const float* wr = Wih0 + (size_t)j * MCW + DD;
    const float* p0 = initp + (size_t)b * 85;
    float s = 0.f;
    for (int m = 0; m < NJ3v; m++) s += p0[m] * wr[m];
    g_p0c[idx] = s;
}

__global__ void packA_kernel(const float* __restrict__ Whh0, const float* __restrict__ Wih0,
                             const float* __restrict__ dec_W) {
    int idx = blockIdx.x * 256 + threadIdx.x;
    int j = idx >> 10, k = idx & (KTOT - 1);
    float v;
    if (k < DD) {
        v = Whh0[(size_t)j * DD + k];
    } else {
        int kk = k - DD;
        const float* wr = Wih0 + (size_t)j * MCW + DD;
        const float* dr = dec_W + (size_t)kk * NJ3v;
        float s = 0.f;
        for (int m = 0; m < NJ3v; m++) s += wr[m] * dr[m];
        v = s;
    }
    g_WA[idx] = v;
}

__global__ void packB_kernel(const float* __restrict__ Wih1, const float* __restrict__ Whh1) {
    int idx = blockIdx.x * 256 + threadIdx.x;
    int j = idx >> 10, k = idx & (KTOT - 1);
    g_WB[idx] = (k < DD) ? Wih1[(size_t)j * DD + k] : Whh1[(size_t)j * DD + (k - DD)];
}

__global__ void init1_kernel(const float* __restrict__ initp, const float* __restrict__ W,
                             const float* __restrict__ b) {
    int idx = blockIdx.x * 256 + threadIdx.x;
    int bb = idx >> 9, j = idx & (DD - 1);
    float s = b[j];
    const float* ir = initp + (size_t)bb * 85;
    for (int i = 0; i < 85; i++) s += ir[i] * W[(size_t)i * DD + j];
    g_z1[idx] = fmaxf(s, 0.f);
}
__global__ void init2_kernel(const float* __restrict__ W, const float* __restrict__ b) {
    int idx = blockIdx.x * 256 + threadIdx.x;
    int bb = idx >> 10, j = idx & 1023;
    float s = b[j];
    const float* zr = g_z1 + (size_t)bb * DD;
    for (int k = 0; k < DD; k++) s += zr[k] * W[(size_t)k * 1024 + j];
    g_z2[idx] = fmaxf(s, 0.f);
}
__global__ void init3_kernel(const float* __restrict__ W, const float* __restrict__ b) {
    int idx = blockIdx.x * 256 + threadIdx.x;
    int bb = idx >> 11, j = idx & (G4 - 1);
    float s = b[j];
    const float* zr = g_z2 + (size_t)bb * 1024;
    for (int k = 0; k < 1024; k++) s += zr[k] * W[(size_t)k * G4 + j];
    if (j < DD)            g_h0[0][(size_t)bb * DD + j] = __float2half(s);
    else if (j < 2 * DD)   g_h1[0][(size_t)bb * DD + (j - DD)] = __float2half(s);
    else if (j < 3 * DD)   g_c0[(size_t)bb * DD + (j - 2 * DD)] = s;
    else                   g_c1[(size_t)bb * DD + (j - 3 * DD)] = s;
}

// Xp in blocked layout: addr = ((t*64 + dg)*256 + b)*32 + g*8 + dl
// where j (global gate row) = g*512 + dg*8 + dl
__global__ void xp_kernel(const float* __restrict__ x) {
    __shared__ float sX[32][INDIM];
    int j = blockIdx.x * 256 + threadIdx.x;  // grid.x = 8
    int r0 = blockIdx.y * 32;
    for (int idx = threadIdx.x; idx < 32 * INDIM; idx += 256) {
        int r = idx / INDIM, i = idx % INDIM;
        int row = r0 + r;
        int tt = row >> 8, b = row & 255;
        sX[r][i] = x[((size_t)b * FF + tt) * INDIM + i];
    }
    __syncthreads();
    float wcol[INDIM];
#pragma unroll
    for (int i = 0; i < INDIM; i++) wcol[i] = g_Wx[i * G4 + j];
    float bxj = g_bx[j], cpj = g_cpred[j];
    int dg = (j & 511) >> 3, dl = j & 7, g = j >> 9;
    int colidx = g * 8 + dl;
    for (int r = 0; r < 32; r++) {
        int row = r0 + r;
        int tt = row >> 8, b = row & 255;
        float acc = bxj + ((tt == 0) ? g_p0c[(size_t)b * G4 + j] : cpj);
#pragma unroll
        for (int i = 0; i < INDIM; i++) acc += sX[r][i] * wcol[i];
        g_Xp[(((size_t)tt * 64 + dg) * 256 + b) * 32 + colidx] = acc;
    }
}

// ---------------- persistent tensor-core recurrent kernel ----------------
// 128 blocks = 64 d-groups x 2 batch halves. Block owns 32 gate rows (4 gates x
// 8 d) of both weight matrices, fp16-resident in SMEM, and 128 batches.
// Per phase: cp.async.cg double-buffered input staging (fp16), mma.sync
// m16n8k16 GEMM (8 warps x 16 batches), fully-register LSTM cell epilogue.

__device__ __forceinline__ void gridbar(unsigned target) {
    __threadfence();
    __syncthreads();
    if (threadIdx.x == 0) {
        unsigned* bp = &g_bar;
        asm volatile("red.release.gpu.add.u32 [%0], 1;" :: "l"(bp) : "memory");
        unsigned v;
        do {
            asm volatile("ld.acquire.gpu.u32 %0, [%1];" : "=r"(v) : "l"(bp) : "memory");
        } while (v < target);
    }
    __syncthreads();
}

__device__ __forceinline__ void stage_tile(const __half* in0, const __half* in1,
                                           int kt, __half* dst, int tid, int B0) {
    const __half* src = ((kt < 8) ? in0 : in1) + (size_t)B0 * DD + (kt & 7) * 64;
#pragma unroll
    for (int i = 0; i < 4; i++) {
        int id = tid + i * 256;
        int br = id >> 3, ch = id & 7;
        unsigned sa = (unsigned)__cvta_generic_to_shared(dst + br * APAD + ch * 8);
        const void* gp = src + (size_t)br * DD + ch * 8;
        asm volatile("cp.async.cg.shared.global [%0], [%1], 16;" :: "r"(sa), "l"(gp));
    }
    asm volatile("cp.async.commit_group;" ::: "memory");
}

template<bool ISA>
__device__ __forceinline__ void do_phase(
    int t, const __half* __restrict__ in0, const __half* __restrict__ in1,
    __half* __restrict__ hout, float* cell, float* __restrict__ mc,
    const __half* sW, __half* sIn, const float* sBias,
    int tid, int wm, int g, int tg, int B0, int d0, int dgrp)
{
    // prefetch gate bases (phase A: Xp from DRAM; phase B: bias from SMEM)
    float2 xb[4][2];
    if (ISA) {
        const float* xp = g_Xp + ((size_t)t * 64 + dgrp) * (256 * 32);
#pragma unroll
        for (int nt = 0; nt < 4; nt++)
#pragma unroll
            for (int p = 0; p < 2; p++) {
                int bl = wm * 16 + g + p * 8;
                xb[nt][p] = __ldcg((const float2*)&xp[(size_t)(B0 + bl) * 32 + nt * 8 + 2 * tg]);
            }
    } else {
#pragma unroll
        for (int nt = 0; nt < 4; nt++) {
            float2 bv;
            bv.x = sBias[nt * 8 + 2 * tg];
            bv.y = sBias[nt * 8 + 2 * tg + 1];
            xb[nt][0] = bv; xb[nt][1] = bv;
        }
    }

    float acc[4][4];
#pragma unroll
    for (int nt = 0; nt < 4; nt++)
#pragma unroll
        for (int r = 0; r < 4; r++) acc[nt][r] = 0.f;

    stage_tile(in0, in1, 0, sIn, tid, B0);

    for (int kt = 0; kt < 16; kt++) {
        if (kt < 15) {
            stage_tile(in0, in1, kt + 1, sIn + ((kt + 1) & 1) * (128 * APAD), tid, B0);
            asm volatile("cp.async.wait_group 1;" ::: "memory");
        } else {
            asm volatile("cp.async.wait_group 0;" ::: "memory");
        }
        __syncthreads();
        const __half* ab = sIn + (kt & 1) * (128 * APAD) + (wm * 16 + g) * APAD + 2 * tg;
        const __half* wb = sW + kt * 64 + 2 * tg;
#pragma unroll
        for (int ks = 0; ks < 4; ks++) {
            unsigned a0 = *(const unsigned*)(ab + ks * 16);
            unsigned a1 = *(const unsigned*)(ab + 8 * APAD + ks * 16);
            unsigned a2 = *(const unsigned*)(ab + ks * 16 + 8);
            unsigned a3 = *(const unsigned*)(ab + 8 * APAD + ks * 16 + 8);
#pragma unroll
            for (int nt = 0; nt < 4; nt++) {
                const __half* bp = wb + (nt * 8 + g) * WPADK + ks * 16;
                unsigned b0 = *(const unsigned*)(bp);
                unsigned b1 = *(const unsigned*)(bp + 8);
                mma16816(acc[nt], a0, a1, a2, a3, b0, b1);
            }
        }
        __syncthreads();
    }

    // register epilogue: thread owns (batch g, g+8) x (d 2tg, 2tg+1), all 4 gates
#pragma unroll
    for (int p = 0; p < 2; p++) {
        int bl = wm * 16 + g + p * 8;
        float hv[2];
#pragma unroll
        for (int v = 0; v < 2; v++) {
            float bi = v ? xb[0][p].y : xb[0][p].x;
            float bf = v ? xb[1][p].y : xb[1][p].x;
            float bg = v ? xb[2][p].y : xb[2][p].x;
            float bo = v ? xb[3][p].y : xb[3][p].x;
            float gi = acc[0][p * 2 + v] + bi;
            float gf = acc[1][p * 2 + v] + bf;
            float gg = acc[2][p * 2 + v] + bg;
            float go = acc[3][p * 2 + v] + bo;
            int ci = bl * 8 + 2 * tg + v;
            float c = cell[ci];
            float cn = sigf(gf) * c + sigf(gi) * tanhf(gg);
            cell[ci] = cn;
            hv[v] = sigf(go) * tanhf(cn);
        }
        __half2 hh = __floats2half2_rn(hv[0], hv[1]);
        *(__half2*)&hout[(size_t)(B0 + bl) * DD + d0 + 2 * tg] = hh;
        if (!ISA) {
            float* mr = mc + ((size_t)(B0 + bl) * FF + t) * MCW + d0 + 2 * tg;
            mr[0] = hv[0]; mr[1] = hv[1];
        }
    }
}

__global__ __launch_bounds__(NTHR, 1) void lstm_persist(float* __restrict__ mc) {
    extern __shared__ __align__(16) unsigned char smraw[];
    __half* sW   = (__half*)smraw;                  // [2][32][WPADK]
    __half* sIn  = sW + 2 * 32 * WPADK;             // [2][128][APAD]
    float*  sC   = (float*)(sIn + 2 * 128 * APAD);  // [2][128*8]
    float*  sBias = sC + 2 * 1024;                  // [32]

    const int tid  = threadIdx.x;
    const int lane = tid & 31;
    const int wm   = tid >> 5;          // warp = m-tile of 16 batches
    const int g    = lane >> 2;
    const int tg   = lane & 3;
    const int dgrp = blockIdx.x >> 1;   // 0..63
    const int B0   = (blockIdx.x & 1) * 128;
    const int d0   = dgrp * 8;

    // one-time: load + convert resident weights (row r = gate*8 + dl)
    for (int i = tid; i < 32 * 1024; i += NTHR) {
        int r = i >> 10, k = i & 1023;
        int grow = (r >> 3) * DD + d0 + (r & 7);
        sW[r * WPADK + k]             = __float2half(__ldcg(&g_WA[(size_t)grow * KTOT + k]));
        sW[32 * WPADK + r * WPADK + k] = __float2half(__ldcg(&g_WB[(size_t)grow * KTOT + k]));
    }
    // one-time: resident c-state + bias
    for (int i = tid; i < 1024; i += NTHR) {
        int bl = i >> 3, dl = i & 7;
        sC[i]        = __ldcg(&g_c0[(size_t)(B0 + bl) * DD + d0 + dl]);
        sC[1024 + i] = __ldcg(&g_c1[(size_t)(B0 + bl) * DD + d0 + dl]);
    }
    if (tid < 32) sBias[tid] = __ldcg(&g_bias1[(tid >> 3) * DD + d0 + (tid & 7)]);
    __syncthreads();

    unsigned ep = 0;
    for (int t = 0; t < FF; t++) {
        int p = t & 1;
        // phase A: layer-0; in = [h0_prev | h1_prev] (Wcomb absorbs pred path)
        do_phase<true>(t, g_h0[p], g_h1[p], g_h0[1 - p], sC, nullptr,
                       sW, sIn, sBias, tid, wm, g, tg, B0, d0, dgrp);
        ep++; gridbar(ep * NBLK);
        // phase B: layer-1; in = [h0_new | h1_prev]; h1 -> motion_context
        do_phase<false>(t, g_h0[1 - p], g_h1[p], g_h1[1 - p], sC + 1024, mc,
                        sW + 32 * WPADK, sIn, sBias, tid, wm, g, tg, B0, d0, dgrp);
        if (t != FF - 1) { ep++; gridbar(ep * NBLK); }
    }
}

// ---------------- final decode: preds from stored h1 context ----------------
__global__ __launch_bounds__(256) void dec_kernel(const float* __restrict__ dec_W,
                                                  const float* __restrict__ dec_b,
                                                  float* __restrict__ out_kp, float* __restrict__ mc) {
    __shared__ float sh[4][DD];
    size_t row0 = (size_t)blockIdx.x * 4;
    for (int idx = threadIdx.x; idx < 4 * DD; idx += 256)
        sh[idx >> 9][idx & (DD - 1)] = mc[(row0 + (idx >> 9)) * MCW + (idx & (DD - 1))];
    __syncthreads();
    int r = threadIdx.x >> 6, c = threadIdx.x & 63;
    if (c < NJ3v) {
        float s = dec_b[c];
        for (int k = 0; k < DD; k++) s += sh[r][k] * dec_W[(size_t)k * NJ3v + c];
        size_t row = row0 + r;
        out_kp[row * NJ3v + c] = s;
        mc[row * MCW + DD + c] = s;
    }
}

// ---------------- launch ----------------
extern "C" void kernel_launch(void* const* d_in, const int* in_sizes, int n_in,
                              void* d_out, int out_size) {
    const float* x       = (const float*)d_in[0];
    const float* initp   = (const float*)d_in[1];
    const float* embed_W = (const float*)d_in[2];
    const float* embed_b = (const float*)d_in[3];
    const float* ni_W1   = (const float*)d_in[4];
    const float* ni_b1   = (const float*)d_in[5];
    const float* ni_W2   = (const float*)d_in[6];
    const float* ni_b2   = (const float*)d_in[7];
    const float* ni_W3   = (const float*)d_in[8];
    const float* ni_b3   = (const float*)d_in[9];
    const float* Wih0    = (const float*)d_in[10];
    const float* Whh0    = (const float*)d_in[11];
    const float* bih0    = (const float*)d_in[12];
    const float* bhh0    = (const float*)d_in[13];
    const float* Wih1    = (const float*)d_in[14];
    const float* Whh1    = (const float*)d_in[15];
    const float* bih1    = (const float*)d_in[16];
    const float* bhh1    = (const float*)d_in[17];
    const float* dec_W   = (const float*)d_in[18];
    const float* dec_b   = (const float*)d_in[19];

    float* out = (float*)d_out;
    float* kp = out;                                  // (B,F,17,3)
    float* mc = out + (size_t)BB * FF * NJ3v;         // (B,F,563)

    // one-time precompute (parallel)
    wx_kernel<<<272, 256>>>(embed_W, Wih0);
    bias_kernel<<<8, 256>>>(embed_b, Wih0, bih0, bhh0, bih1, bhh1, dec_b);
    p0c_kernel<<<2048, 256>>>(initp, Wih0);
    packA_kernel<<<8192, 256>>>(Whh0, Wih0, dec_W);
    packB_kernel<<<8192, 256>>>(Wih1, Whh1);
    init1_kernel<<<512, 256>>>(initp, ni_W1, ni_b1);
    init2_kernel<<<1024, 256>>>(ni_W2, ni_b2);
    init3_kernel<<<2048, 256>>>(ni_W3, ni_b3);
    xp_kernel<<<dim3(8, 2048), 256>>>(x);

    // reset grid barrier counter (graph-replay deterministic)
    void* barp = nullptr;
    cudaGetSymbolAddress(&barp, g_bar);
    cudaMemsetAsync(barp, 0, sizeof(unsigned));

    // persistent tensor-core recurrence
    const int SMEM_TOT = (2 * 32 * WPADK + 2 * 128 * APAD) * 2 + (2 * 1024 + 32) * 4;
    static int attr_set = 0;
    if (!attr_set) {
        cudaFuncSetAttribute(lstm_persist, cudaFuncAttributeMaxDynamicSharedMemorySize, SMEM_TOT);
        attr_set = 1;
    }
    lstm_persist<<<NBLK, NTHR, SMEM_TOT>>>(mc);

    // final decode of preds for all (b,t)
    dec_kernel<<<16384, 256>>>(dec_W, dec_b, kp, mc);
}

// round 13
// speedup vs baseline: 5.0165x; 1.1382x over previous
#include <cuda_runtime.h>
#include <cuda_fp16.h>
#include <math.h>

#define BB 256
#define FF 256
#define DD 512
#define NJ3v 51
#define INDIM 34
#define G4 2048       // 4*D gate rows
#define KTOT 1024     // packed K (512 + 512)
#define MCW 563       // D + NJ3
#define NBLK 128
#define NTHR 256
#define WPADK 1032    // weight SMEM k-stride (pad for conflict-free B-frag loads)
#define APAD 72       // input SMEM k-stride (64 + 8 pad)
#define TILEH (128 * APAD)   // halves per input buffer

// ---------------- static device scratch (no runtime allocation) ----------------
__device__ float g_Xp[(size_t)BB * FF * G4];   // blocked layout [t][dg64][b256][32]
__device__ float g_WA[(size_t)G4 * KTOT];      // [Whh0 | Wcomb]  fp32
__device__ float g_WB[(size_t)G4 * KTOT];      // [Wih1 | Whh1]   fp32
__device__ float g_Wx[INDIM * G4];             // embed_W @ Wih0x^T
__device__ float g_bx[G4];
__device__ float g_cpred[G4];                  // dec_b @ Wih0pred^T
__device__ float g_bias1[G4];
__device__ float g_p0c[BB * G4];               // pred0 @ Wih0pred^T
__device__ __half g_h0[2][BB * DD];            // h states, fp16
__device__ __half g_h1[2][BB * DD];
__device__ float g_c0[BB * DD];
__device__ float g_c1[BB * DD];
__device__ float g_z1[BB * DD];
__device__ float g_z2[BB * 1024];
__device__ unsigned g_bar2[64];                // [0], [32]: per-batch-half counters

// ---------------- helpers ----------------
__device__ __forceinline__ float sigf(float x) { return 1.0f / (1.0f + expf(-x)); }

__device__ __forceinline__ void mma16816(float* d,
    unsigned a0, unsigned a1, unsigned a2, unsigned a3,
    unsigned b0, unsigned b1) {
    asm volatile(
        "mma.sync.aligned.m16n8k16.row.col.f32.f16.f16.f32 "
        "{%0,%1,%2,%3}, {%4,%5,%6,%7}, {%8,%9}, {%0,%1,%2,%3};"
        : "+f"(d[0]), "+f"(d[1]), "+f"(d[2]), "+f"(d[3])
        : "r"(a0), "r"(a1), "r"(a2), "r"(a3), "r"(b0), "r"(b1));
}

// ---------------- one-time precompute kernels (off critical path) ----------------

__global__ void wx_kernel(const float* __restrict__ embed_W, const float* __restrict__ Wih0) {
    int idx = blockIdx.x * 256 + threadIdx.x;
    if (idx >= INDIM * G4) return;
    int i = idx / G4, j = idx % G4;
    float s = 0.f;
    const float* wr = Wih0 + (size_t)j * MCW;
    const float* er = embed_W + (size_t)i * DD;
    for (int k = 0; k < DD; k++) s += er[k] * wr[k];
    g_Wx[idx] = s;
}

__global__ void bias_kernel(const float* __restrict__ embed_b, const float* __restrict__ Wih0,
                            const float* __restrict__ bih0, const float* __restrict__ bhh0,
                            const float* __restrict__ bih1, const float* __restrict__ bhh1,
                            const float* __restrict__ dec_b) {
    int j = blockIdx.x * 256 + threadIdx.x;
    if (j >= G4) return;
    const float* wr = Wih0 + (size_t)j * MCW;
    float s = bih0[j] + bhh0[j];
    for (int k = 0; k < DD; k++) s += embed_b[k] * wr[k];
    g_bx[j] = s;
    float cp = 0.f;
    for (int m = 0; m < NJ3v; m++) cp += dec_b[m] * wr[DD + m];
    g_cpred[j] = cp;
    g_bias1[j] = bih1[j] + bhh1[j];
}

__global__ void p0c_kernel(const float* __restrict__ initp, const float* __restrict__ Wih0) {
    int idx = blockIdx.x * 256 + threadIdx.x;
    int b = idx >> 11, j = idx & (G4 - 1);
    const float* wr = Wih0 + (size_t)j * MCW + DD;
    const float* p0 = initp + (size_t)b * 85;
    float s = 0.f;
    for (int m = 0; m < NJ3v; m++) s += p0[m] * wr[m];
    g_p0c[idx] = s;
}

__global__ void packA_kernel(const float* __restrict__ Whh0, const float* __restrict__ Wih0,
                             const float* __restrict__ dec_W) {
    int idx = blockIdx.x * 256 + threadIdx.x;
    int j = idx >> 10, k = idx & (KTOT - 1);
    float v;
    if (k < DD) {
        v = Whh0[(size_t)j * DD + k];
    } else {
        int kk = k - DD;
        const float* wr = Wih0 + (size_t)j * MCW + DD;
        const float* dr = dec_W + (size_t)kk * NJ3v;
        float s = 0.f;
        for (int m = 0; m < NJ3v; m++) s += wr[m] * dr[m];
        v = s;
    }
    g_WA[idx] = v;
}

__global__ void packB_kernel(const float* __restrict__ Wih1, const float* __restrict__ Whh1) {
    int idx = blockIdx.x * 256 + threadIdx.x;
    int j = idx >> 10, k = idx & (KTOT - 1);
    g_WB[idx] = (k < DD) ? Wih1[(size_t)j * DD + k] : Whh1[(size_t)j * DD + (k - DD)];
}

__global__ void init1_kernel(const float* __restrict__ initp, const float* __restrict__ W,
                             const float* __restrict__ b) {
    int idx = blockIdx.x * 256 + threadIdx.x;
    int bb = idx >> 9, j = idx & (DD - 1);
    float s = b[j];
    const float* ir = initp + (size_t)bb * 85;
    for (int i = 0; i < 85; i++) s += ir[i] * W[(size_t)i * DD + j];
    g_z1[idx] = fmaxf(s, 0.f);
}
__global__ void init2_kernel(const float* __restrict__ W, const float* __restrict__ b) {
    int idx = blockIdx.x * 256 + threadIdx.x;
    int bb = idx >> 10, j = idx & 1023;
    float s = b[j];
    const float* zr = g_z1 + (size_t)bb * DD;
    for (int k = 0; k < DD; k++) s += zr[k] * W[(size_t)k * 1024 + j];
    g_z2[idx] = fmaxf(s, 0.f);
}
__global__ void init3_kernel(const float* __restrict__ W, const float* __restrict__ b) {
    int idx = blockIdx.x * 256 + threadIdx.x;
    int bb = idx >> 11, j = idx & (G4 - 1);
    float s = b[j];
    const float* zr = g_z2 + (size_t)bb * 1024;
    for (int k = 0; k < 1024; k++) s += zr[k] * W[(size_t)k * G4 + j];
    if (j < DD)            g_h0[0][(size_t)bb * DD + j] = __float2half(s);
    else if (j < 2 * DD)   g_h1[0][(size_t)bb * DD + (j - DD)] = __float2half(s);
    else if (j < 3 * DD)   g_c0[(size_t)bb * DD + (j - 2 * DD)] = s;
    else                   g_c1[(size_t)bb * DD + (j - 3 * DD)] = s;
}

// Xp in blocked layout: addr = ((t*64 + dg)*256 + b)*32 + g*8 + dl
__global__ void xp_kernel(const float* __restrict__ x) {
    __shared__ float sX[32][INDIM];
    int j = blockIdx.x * 256 + threadIdx.x;  // grid.x = 8
    int r0 = blockIdx.y * 32;
    for (int idx = threadIdx.x; idx < 32 * INDIM; idx += 256) {
        int r = idx / INDIM, i = idx % INDIM;
        int row = r0 + r;
        int tt = row >> 8, b = row & 255;
        sX[r][i] = x[((size_t)b * FF + tt) * INDIM + i];
    }
    __syncthreads();
    float wcol[INDIM];
#pragma unroll
    for (int i = 0; i < INDIM; i++) wcol[i] = g_Wx[i * G4 + j];
    float bxj = g_bx[j], cpj = g_cpred[j];
    int dg = (j & 511) >> 3, dl = j & 7, g = j >> 9;
    int colidx = g * 8 + dl;
    for (int r = 0; r < 32; r++) {
        int row = r0 + r;
        int tt = row >> 8, b = row & 255;
        float acc = bxj + ((tt == 0) ? g_p0c[(size_t)b * G4 + j] : cpj);
#pragma unroll
        for (int i = 0; i < INDIM; i++) acc += sX[r][i] * wcol[i];
        g_Xp[(((size_t)tt * 64 + dg) * 256 + b) * 32 + colidx] = acc;
    }
}

// ---------------- persistent tensor-core recurrent kernel ----------------
// 128 blocks = 64 d-groups x 2 batch halves. 4-deep cp.async pipeline,
// per-batch-half split barrier overlapped with the safe input half.

__device__ __forceinline__ void bar_arrive(int bh) {
    __threadfence();
    if (threadIdx.x == 0) {
        unsigned* bp = &g_bar2[bh * 32];
        asm volatile("red.release.gpu.add.u32 [%0], 1;" :: "l"(bp) : "memory");
    }
}
__device__ __forceinline__ void bar_wait(int bh, unsigned target) {
    if (threadIdx.x == 0) {
        unsigned* bp = &g_bar2[bh * 32];
        unsigned v;
        asm volatile("ld.acquire.gpu.u32 %0, [%1];" : "=r"(v) : "l"(bp) : "memory");
        while (v < target) {
            asm volatile("nanosleep.u32 64;");
            asm volatile("ld.acquire.gpu.u32 %0, [%1];" : "=r"(v) : "l"(bp) : "memory");
        }
    }
    __syncthreads();
}

__device__ __forceinline__ void stage_tile(const __half* in0, const __half* in1,
                                           int ktile, __half* dst, int tid, int B0) {
    const __half* src = ((ktile < 8) ? in0 : in1) + (size_t)B0 * DD + (ktile & 7) * 64;
#pragma unroll
    for (int i = 0; i < 4; i++) {
        int id = tid + i * 256;
        int br = id >> 3, ch = id & 7;
        unsigned sa = (unsigned)__cvta_generic_to_shared(dst + br * APAD + ch * 8);
        const void* gp = src + (size_t)br * DD + ch * 8;
        asm volatile("cp.async.cg.shared.global [%0], [%1], 16;" :: "r"(sa), "l"(gp));
    }
    asm volatile("cp.async.commit_group;" ::: "memory");
}

__device__ __forceinline__ void consume_tile(float acc[4][4], const __half* abuf,
                                             const __half* sW, int ktile,
                                             int wm, int g, int tg) {
    const __half* ab = abuf + (wm * 16 + g) * APAD + 2 * tg;
    const __half* wb = sW + ktile * 64 + 2 * tg;
#pragma unroll
    for (int ks = 0; ks < 4; ks++) {
        unsigned a0 = *(const unsigned*)(ab + ks * 16);
        unsigned a1 = *(const unsigned*)(ab + 8 * APAD + ks * 16);
        unsigned a2 = *(const unsigned*)(ab + ks * 16 + 8);
        unsigned a3 = *(const unsigned*)(ab + 8 * APAD + ks * 16 + 8);
#pragma unroll
        for (int nt = 0; nt < 4; nt++) {
            const __half* bp = wb + (nt * 8 + g) * WPADK + ks * 16;
            unsigned b0 = *(const unsigned*)(bp);
            unsigned b1 = *(const unsigned*)(bp + 8);
            mma16816(acc[nt], a0, a1, a2, a3, b0, b1);
        }
    }
}

// koff: k-tile rotation (0 for phase A, 8 for phase B) so the barrier-safe
// input half is staged/computed first. target==0 -> no barrier wait.
template<bool ISA>
__device__ __forceinline__ void do_phase(
    int t, int koff, const __half* __restrict__ in0, const __half* __restrict__ in1,
    __half* __restrict__ hout, float* cell, float* __restrict__ mc,
    const __half* sW, __half* sIn, const float* sBias,
    int tid, int wm, int g, int tg, int B0, int d0, int dgrp,
    int bh, unsigned target)
{
    // gate bases (phase A: Xp from DRAM; phase B: bias from SMEM)
    float2 xb[4][2];
    if (ISA) {
        const float* xp = g_Xp + ((size_t)t * 64 + dgrp) * (256 * 32);
#pragma unroll
        for (int nt = 0; nt < 4; nt++)
#pragma unroll
            for (int p = 0; p < 2; p++) {
                int bl = wm * 16 + g + p * 8;
                xb[nt][p] = __ldcg((const float2*)&xp[(size_t)(B0 + bl) * 32 + nt * 8 + 2 * tg]);
            }
    } else {
#pragma unroll
        for (int nt = 0; nt < 4; nt++) {
            float2 bv;
            bv.x = sBias[nt * 8 + 2 * tg];
            bv.y = sBias[nt * 8 + 2 * tg + 1];
            xb[nt][0] = bv; xb[nt][1] = bv;
        }
    }

    float acc[4][4];
#pragma unroll
    for (int nt = 0; nt < 4; nt++)
#pragma unroll
        for (int r = 0; r < 4; r++) acc[nt][r] = 0.f;

    // prologue: stage 3 safe tiles
    stage_tile(in0, in1, (0 + koff) & 15, sIn + 0 * TILEH, tid, B0);
    stage_tile(in0, in1, (1 + koff) & 15, sIn + 1 * TILEH, tid, B0);
    stage_tile(in0, in1, (2 + koff) & 15, sIn + 2 * TILEH, tid, B0);

    for (int i = 0; i < 14; i++) {
        if (i == 5 && target) bar_wait(bh, target);   // before first dependent stage
        asm volatile("cp.async.wait_group 2;" ::: "memory");
        __syncthreads();
        stage_tile(in0, in1, (i + 3 + koff) & 15, sIn + ((i + 3) & 3) * TILEH, tid, B0);
        consume_tile(acc, sIn + (i & 3) * TILEH, sW, (i + koff) & 15, wm, g, tg);
    }
    asm volatile("cp.async.wait_group 1;" ::: "memory");
    __syncthreads();
    consume_tile(acc, sIn + (14 & 3) * TILEH, sW, (14 + koff) & 15, wm, g, tg);
    asm volatile("cp.async.wait_group 0;" ::: "memory");
    __syncthreads();
    consume_tile(acc, sIn + (15 & 3) * TILEH, sW, (15 + koff) & 15, wm, g, tg);

    // register epilogue: thread owns (batch g, g+8) x (d 2tg, 2tg+1), all 4 gates
#pragma unroll
    for (int p = 0; p < 2; p++) {
        int bl = wm * 16 + g + p * 8;
        float hv[2];
#pragma unroll
        for (int v = 0; v < 2; v++) {
            float bi = v ? xb[0][p].y : xb[0][p].x;
            float bf = v ? xb[1][p].y : xb[1][p].x;
            float bg = v ? xb[2][p].y : xb[2][p].x;
            float bo = v ? xb[3][p].y : xb[3][p].x;
            float gi = acc[0][p * 2 + v] + bi;
            float gf = acc[1][p * 2 + v] + bf;
            float gg = acc[2][p * 2 + v] + bg;
            float go = acc[3][p * 2 + v] + bo;
            int ci = bl * 8 + 2 * tg + v;
            float c = cell[ci];
            float cn = sigf(gf) * c + sigf(gi) * tanhf(gg);
            cell[ci] = cn;
            hv[v] = sigf(go) * tanhf(cn);
        }
        __half2 hh = __floats2half2_rn(hv[0], hv[1]);
        *(__half2*)&hout[(size_t)(B0 + bl) * DD + d0 + 2 * tg] = hh;
        if (!ISA) {
            float* mr = mc + ((size_t)(B0 + bl) * FF + t) * MCW + d0 + 2 * tg;
            mr[0] = hv[0]; mr[1] = hv[1];
        }
    }
}

__global__ __launch_bounds__(NTHR, 1) void lstm_persist(float* __restrict__ mc) {
    extern __shared__ __align__(16) unsigned char smraw[];
    __half* sW    = (__half*)smraw;                  // [2][32][WPADK]
    __half* sIn   = sW + 2 * 32 * WPADK;             // [4][128][APAD]
    float*  sC    = (float*)(sIn + 4 * TILEH);       // [2][128*8]
    float*  sBias = sC + 2 * 1024;                   // [32]

    const int tid  = threadIdx.x;
    const int lane = tid & 31;
    const int wm   = tid >> 5;          // warp = m-tile of 16 batches
    const int g    = lane >> 2;
    const int tg   = lane & 3;
    const int dgrp = blockIdx.x >> 1;   // 0..63
    const int bh   = blockIdx.x & 1;    // batch half
    const int B0   = bh * 128;
    const int d0   = dgrp * 8;

    // one-time: load + convert resident weights (row r = gate*8 + dl)
    for (int i = tid; i < 32 * 1024; i += NTHR) {
        int r = i >> 10, k = i & 1023;
        int grow = (r >> 3) * DD + d0 + (r & 7);
        sW[r * WPADK + k]              = __float2half(__ldcg(&g_WA[(size_t)grow * KTOT + k]));
        sW[32 * WPADK + r * WPADK + k] = __float2half(__ldcg(&g_WB[(size_t)grow * KTOT + k]));
    }
    // one-time: resident c-state + bias
    for (int i = tid; i < 1024; i += NTHR) {
        int bl = i >> 3, dl = i & 7;
        sC[i]        = __ldcg(&g_c0[(size_t)(B0 + bl) * DD + d0 + dl]);
        sC[1024 + i] = __ldcg(&g_c1[(size_t)(B0 + bl) * DD + d0 + dl]);
    }
    if (tid < 32) sBias[tid] = __ldcg(&g_bias1[(tid >> 3) * DD + d0 + (tid & 7)]);
    __syncthreads();

    unsigned ep = 0;
    for (int t = 0; t < FF; t++) {
        int p = t & 1;
        // phase A: layer-0; in = [h0_prev | h1_prev]; safe half = h0 (k 0-511)
        do_phase<true>(t, 0, g_h0[p], g_h1[p], g_h0[1 - p], sC, nullptr,
                       sW, sIn, sBias, tid, wm, g, tg, B0, d0, dgrp,
                       bh, ep ? ep * 64u : 0u);
        __syncthreads();
        bar_arrive(bh); ep++;
        // phase B: layer-1; in = [h0_new | h1_prev]; safe half = h1 (k 512-1023)
        do_phase<false>(t, 8, g_h0[1 - p], g_h1[p], g_h1[1 - p], sC + 1024, mc,
                        sW + 32 * WPADK, sIn, sBias, tid, wm, g, tg, B0, d0, dgrp,
                        bh, ep * 64u);
        __syncthreads();
        bar_arrive(bh); ep++;
    }
}

// ---------------- final decode: preds from stored h1 context ----------------
__global__ __launch_bounds__(256) void dec_kernel(const float* __restrict__ dec_W,
                                                  const float* __restrict__ dec_b,
                                                  float* __restrict__ out_kp, float* __restrict__ mc) {
    __shared__ float sh[4][DD];
    size_t row0 = (size_t)blockIdx.x * 4;
    for (int idx = threadIdx.x; idx < 4 * DD; idx += 256)
        sh[idx >> 9][idx & (DD - 1)] = mc[(row0 + (idx >> 9)) * MCW + (idx & (DD - 1))];
    __syncthreads();
    int r = threadIdx.x >> 6, c = threadIdx.x & 63;
    if (c < NJ3v) {
        float s = dec_b[c];
        for (int k = 0; k < DD; k++) s += sh[r][k] * dec_W[(size_t)k * NJ3v + c];
        size_t row = row0 + r;
        out_kp[row * NJ3v + c] = s;
        mc[row * MCW + DD + c] = s;
    }
}

// ---------------- launch ----------------
extern "C" void kernel_launch(void* const* d_in, const int* in_sizes, int n_in,
                              void* d_out, int out_size) {
    const float* x       = (const float*)d_in[0];
    const float* initp   = (const float*)d_in[1];
    const float* embed_W = (const float*)d_in[2];
    const float* embed_b = (const float*)d_in[3];
    const float* ni_W1   = (const float*)d_in[4];
    const float* ni_b1   = (const float*)d_in[5];
    const float* ni_W2   = (const float*)d_in[6];
    const float* ni_b2   = (const float*)d_in[7];
    const float* ni_W3   = (const float*)d_in[8];
    const float* ni_b3   = (const float*)d_in[9];
    const float* Wih0    = (const float*)d_in[10];
    const float* Whh0    = (const float*)d_in[11];
    const float* bih0    = (const float*)d_in[12];
    const float* bhh0    = (const float*)d_in[13];
    const float* Wih1    = (const float*)d_in[14];
    const float* Whh1    = (const float*)d_in[15];
    const float* bih1    = (const float*)d_in[16];
    const float* bhh1    = (const float*)d_in[17];
    const float* dec_W   = (const float*)d_in[18];
    const float* dec_b   = (const float*)d_in[19];

    float* out = (float*)d_out;
    float* kp = out;                                  // (B,F,17,3)
    float* mc = out + (size_t)BB * FF * NJ3v;         // (B,F,563)

    // one-time precompute (parallel)
    wx_kernel<<<272, 256>>>(embed_W, Wih0);
    bias_kernel<<<8, 256>>>(embed_b, Wih0, bih0, bhh0, bih1, bhh1, dec_b);
    p0c_kernel<<<2048, 256>>>(initp, Wih0);
    packA_kernel<<<8192, 256>>>(Whh0, Wih0, dec_W);
    packB_kernel<<<8192, 256>>>(Wih1, Whh1);
    init1_kernel<<<512, 256>>>(initp, ni_W1, ni_b1);
    init2_kernel<<<1024, 256>>>(ni_W2, ni_b2);
    init3_kernel<<<2048, 256>>>(ni_W3, ni_b3);
    xp_kernel<<<dim3(8, 2048), 256>>>(x);

    // reset split barrier counters (graph-replay deterministic)
    void* barp = nullptr;
    cudaGetSymbolAddress(&barp, g_bar2);
    cudaMemsetAsync(barp, 0, 64 * sizeof(unsigned));

    // persistent tensor-core recurrence
    const int SMEM_TOT = (2 * 32 * WPADK + 4 * TILEH) * 2 + (2 * 1024 + 32) * 4;
    static int attr_set = 0;
    if (!attr_set) {
        cudaFuncSetAttribute(lstm_persist, cudaFuncAttributeMaxDynamicSharedMemorySize, SMEM_TOT);
        attr_set = 1;
    }
    lstm_persist<<<NBLK, NTHR, SMEM_TOT>>>(mc);

    // final decode of preds for all (b,t)
    dec_kernel<<<16384, 256>>>(dec_W, dec_b, kp, mc);
}